// round 12
// baseline (speedup 1.0000x reference)
#include <cuda_runtime.h>
#include <cuda_bf16.h>
#include <cstdint>
#include <cmath>

#define BATCH   4
#define SEQ     1024
#define DM      1024
#define NHEAD   16
#define DK      64
#define MROWS   (BATCH*SEQ)
#define LN_EPS  1e-5f

__device__ float g_Qp[MROWS * DM];
__device__ float g_Kp[MROWS * DM];
__device__ float g_Vp[MROWS * DM];
__device__ float g_heads[MROWS * DM];
__device__ float g_tmp[MROWS * DM];

// ---------------- helpers ----------------
__device__ __forceinline__ void bsplit4(float4 v, uint2& h, uint2& l) {
    __nv_bfloat162 h0 = __floats2bfloat162_rn(v.x, v.y);
    __nv_bfloat162 h1 = __floats2bfloat162_rn(v.z, v.w);
    float r0 = v.x - __bfloat162float(h0.x);
    float r1 = v.y - __bfloat162float(h0.y);
    float r2 = v.z - __bfloat162float(h1.x);
    float r3 = v.w - __bfloat162float(h1.y);
    __nv_bfloat162 l0 = __floats2bfloat162_rn(r0, r1);
    __nv_bfloat162 l1 = __floats2bfloat162_rn(r2, r3);
    h.x = *reinterpret_cast<uint32_t*>(&h0);
    h.y = *reinterpret_cast<uint32_t*>(&h1);
    l.x = *reinterpret_cast<uint32_t*>(&l0);
    l.y = *reinterpret_cast<uint32_t*>(&l1);
}

__device__ __forceinline__ void bsplit2(float a, float b, uint32_t& h, uint32_t& l) {
    __nv_bfloat162 hh = __floats2bfloat162_rn(a, b);
    float ra = a - __bfloat162float(hh.x);
    float rb = b - __bfloat162float(hh.y);
    __nv_bfloat162 ll = __floats2bfloat162_rn(ra, rb);
    h = *reinterpret_cast<uint32_t*>(&hh);
    l = *reinterpret_cast<uint32_t*>(&ll);
}

__device__ __forceinline__ void mma_bf16(float* c, const uint32_t* a, const uint32_t* b) {
    asm volatile(
        "mma.sync.aligned.m16n8k16.row.col.f32.bf16.bf16.f32 "
        "{%0,%1,%2,%3}, {%4,%5,%6,%7}, {%8,%9}, {%0,%1,%2,%3};"
        : "+f"(c[0]), "+f"(c[1]), "+f"(c[2]), "+f"(c[3])
        : "r"(a[0]), "r"(a[1]), "r"(a[2]), "r"(a[3]), "r"(b[0]), "r"(b[1]));
}

__device__ __forceinline__ uint32_t smem_u32(const void* p) {
    return (uint32_t)__cvta_generic_to_shared(p);
}
__device__ __forceinline__ void ldsm_x4(uint32_t* r, uint32_t addr) {
    asm volatile("ldmatrix.sync.aligned.m8n8.x4.shared.b16 {%0,%1,%2,%3}, [%4];"
        : "=r"(r[0]), "=r"(r[1]), "=r"(r[2]), "=r"(r[3]) : "r"(addr));
}

// =====================================================================
// bf16x3 GEMM: BM=128, BN=64, BK=32, ldsm fragments (r7-proven),
// DOUBLE-BUFFERED smem: one __syncthreads per k-iter.
// =====================================================================
#define GW 20
#define APLANE (128 * GW)      // words per A plane buffer
#define BPLANE (64 * GW)       // words per B plane buffer

#define GEMM_LOAD(k0) do { \
    _Pragma("unroll") \
    for (int it = 0; it < 4; it++) { \
        int idx = it * 256 + tid; int r = idx >> 3, c4 = (idx & 7) * 4; \
        sa[it] = *reinterpret_cast<const float4*>(A + (size_t)(bm + r) * DM + (k0) + c4); \
    } \
    _Pragma("unroll") \
    for (int it = 0; it < 2; it++) { \
        int idx = it * 256 + tid; int r = idx >> 3, c4 = (idx & 7) * 4; \
        sb[it] = *reinterpret_cast<const float4*>(W + (size_t)(bn + r) * DM + (k0) + c4); \
    } \
} while (0)

#define GEMM_STORE(bufi) do { \
    _Pragma("unroll") \
    for (int it = 0; it < 4; it++) { \
        int idx = it * 256 + tid; \
        int r = idx >> 3, w = (idx & 7) * 2; \
        uint2 h, l; bsplit4(sa[it], h, l); \
        *reinterpret_cast<uint2*>(&AsH[(bufi) * APLANE + r * GW + w]) = h; \
        *reinterpret_cast<uint2*>(&AsL[(bufi) * APLANE + r * GW + w]) = l; \
    } \
    _Pragma("unroll") \
    for (int it = 0; it < 2; it++) { \
        int idx = it * 256 + tid; \
        int r = idx >> 3, w = (idx & 7) * 2; \
        uint2 h, l; bsplit4(sb[it], h, l); \
        *reinterpret_cast<uint2*>(&BsH[(bufi) * BPLANE + r * GW + w]) = h; \
        *reinterpret_cast<uint2*>(&BsL[(bufi) * BPLANE + r * GW + w]) = l; \
    } \
} while (0)

__device__ __forceinline__ void gemm_core(
    const float* __restrict__ A, const float* __restrict__ W,
    const float* __restrict__ bias, const float* __restrict__ resid,
    float* __restrict__ C, int bm, int bn)
{
    __shared__ uint32_t AsH[2 * APLANE], AsL[2 * APLANE];
    __shared__ uint32_t BsH[2 * BPLANE], BsL[2 * BPLANE];

    const int tid = threadIdx.x;
    const int wid = tid >> 5, lane = tid & 31;
    const int g = lane >> 2, t = lane & 3;
    const int warpM = (wid & 1) * 64;
    const int warpN = (wid >> 1) * 16;

    const uint32_t aoff = (((warpM + (lane & 15)) * GW) + (lane >> 4) * 4) * 4;
    const uint32_t aH_base = smem_u32(AsH) + aoff;
    const uint32_t aL_base = smem_u32(AsL) + aoff;
    const uint32_t boff = (((warpN + (lane & 7) + ((lane >> 4) & 1) * 8) * GW)
                           + ((lane >> 3) & 1) * 4) * 4;
    const uint32_t bH_base = smem_u32(BsH) + boff;
    const uint32_t bL_base = smem_u32(BsL) + boff;

    float c[4][2][4];
    #pragma unroll
    for (int mt = 0; mt < 4; mt++)
        #pragma unroll
        for (int nt = 0; nt < 2; nt++)
            #pragma unroll
            for (int i = 0; i < 4; i++) c[mt][nt][i] = 0.f;

    float4 sa[4], sb[2];
    GEMM_LOAD(0);
    GEMM_STORE(0);
    GEMM_LOAD(32);

    for (int k0 = 0; k0 < DM; k0 += 32) {
        const int buf = (k0 >> 5) & 1;
        __syncthreads();
        if (k0 + 32 < DM) GEMM_STORE(buf ^ 1);
        if (k0 + 64 < DM) GEMM_LOAD(k0 + 64);

        const uint32_t ab = buf * (APLANE * 4);
        const uint32_t bb = buf * (BPLANE * 4);
        #pragma unroll
        for (int ks = 0; ks < 2; ks++) {
            const uint32_t kb = ks * 32;
            uint32_t aH[4][4], aL[4][4], bH[4], bL[4];
            #pragma unroll
            for (int mt = 0; mt < 4; mt++) {
                ldsm_x4(aH[mt], aH_base + ab + mt * (16 * GW * 4) + kb);
                ldsm_x4(aL[mt], aL_base + ab + mt * (16 * GW * 4) + kb);
            }
            ldsm_x4(bH, bH_base + bb + kb);
            ldsm_x4(bL, bL_base + bb + kb);
            #pragma unroll
            for (int mt = 0; mt < 4; mt++)
                #pragma unroll
                for (int nt = 0; nt < 2; nt++) {
                    mma_bf16(c[mt][nt], aH[mt], bH + nt * 2);
                    mma_bf16(c[mt][nt], aH[mt], bL + nt * 2);
                    mma_bf16(c[mt][nt], aL[mt], bH + nt * 2);
                }
        }
    }

    #pragma unroll
    for (int mt = 0; mt < 4; mt++) {
        int r0 = bm + warpM + mt * 16 + g;
        int r1 = r0 + 8;
        #pragma unroll
        for (int nt = 0; nt < 2; nt++) {
            int cn = bn + warpN + nt * 8 + 2 * t;
            float b0 = bias[cn], b1 = bias[cn + 1];
            float v00 = c[mt][nt][0] + b0, v01 = c[mt][nt][1] + b1;
            float v10 = c[mt][nt][2] + b0, v11 = c[mt][nt][3] + b1;
            if (resid) {
                float2 rA = *reinterpret_cast<const float2*>(resid + (size_t)r0 * DM + cn);
                float2 rB = *reinterpret_cast<const float2*>(resid + (size_t)r1 * DM + cn);
                v00 += rA.x; v01 += rA.y; v10 += rB.x; v11 += rB.y;
            }
            *reinterpret_cast<float2*>(C + (size_t)r0 * DM + cn) = make_float2(v00, v01);
            *reinterpret_cast<float2*>(C + (size_t)r1 * DM + cn) = make_float2(v10, v11);
        }
    }
}

__global__ __launch_bounds__(256, 2) void qkv_gemm(
    const float* __restrict__ q, const float* __restrict__ k, const float* __restrict__ v,
    const float* __restrict__ Wq, const float* __restrict__ Wk, const float* __restrict__ Wv,
    const float* __restrict__ bq, const float* __restrict__ bk, const float* __restrict__ bv,
    float* __restrict__ Qp, float* __restrict__ Kp, float* __restrict__ Vp)
{
    const int z = blockIdx.z;
    const float* A = (z == 0) ? q : (z == 1) ? k : v;
    const float* W = (z == 0) ? Wq : (z == 1) ? Wk : Wv;
    const float* B = (z == 0) ? bq : (z == 1) ? bk : bv;
    float* C = (z == 0) ? Qp : (z == 1) ? Kp : Vp;
    gemm_core(A, W, B, nullptr, C, blockIdx.y * 128, blockIdx.x * 64);
}

__global__ __launch_bounds__(256, 2) void out_gemm(
    const float* __restrict__ A, const float* __restrict__ W,
    const float* __restrict__ bias, const float* __restrict__ resid,
    float* __restrict__ C)
{
    gemm_core(A, W, bias, resid, C, blockIdx.y * 128, blockIdx.x * 64);
}

// =====================================================================
// Attention QK + softmax: block = (b, h, 16 q rows), 256 threads.
// Same math as r6's mt=0 path; half the smem -> 2 blocks/SM.
// =====================================================================
#define SLD 1028
#define LW  36
#define VW  35
#define OFF_S   0
#define SZ_S    (16 * SLD * 4)                 // 65792
#define OFF_QP  SZ_S
#define SZ_QP   (2 * 16 * LW * 4)              // 4608
#define OFF_KV  (OFF_QP + SZ_QP)
#define SZ_KV   36864
#define ATTN_SMEM_BYTES (OFF_KV + SZ_KV)       // 107264

__global__ __launch_bounds__(256) void attn_kernel(
    const float* __restrict__ Qp, const float* __restrict__ Kp,
    const float* __restrict__ gate, const int* __restrict__ mask,
    float* __restrict__ attn)
{
    extern __shared__ char smraw[];
    float* S = reinterpret_cast<float*>(smraw + OFF_S);
    uint32_t* QHs = reinterpret_cast<uint32_t*>(smraw + OFF_QP);
    uint32_t* QLs = QHs + 16 * LW;
    uint32_t* KVb = reinterpret_cast<uint32_t*>(smraw + OFF_KV);

    const int b = blockIdx.z, h = blockIdx.y;
    const int q0 = blockIdx.x * 16;
    const int tid = threadIdx.x;
    const int wid = tid >> 5, lane = tid & 31;
    const int g = lane >> 2, t = lane & 3;
    const int n = wid * 8;

    // Q tile [16][64] -> bf16 hi/lo (256 threads, one float4 each)
    {
        int r = tid >> 4, c4 = (tid & 15) * 4;
        float4 v = *reinterpret_cast<const float4*>(
            Qp + (size_t)(b * SEQ + q0 + r) * DM + h * DK + c4);
        uint2 hh, ll; bsplit4(v, hh, ll);
        *reinterpret_cast<uint2*>(&QHs[r * LW + (c4 >> 1)]) = hh;
        *reinterpret_cast<uint2*>(&QLs[r * LW + (c4 >> 1)]) = ll;
    }

    // K chunk 0 -> buf 0
    {
        uint32_t* KH = KVb; uint32_t* KL = KVb + 2304;
        #pragma unroll
        for (int it = 0; it < 4; it++) {
            int idx = it * 256 + tid;
            int r = idx >> 4, c4 = (idx & 15) * 4;
            float4 v = *reinterpret_cast<const float4*>(
                Kp + (size_t)(b * SEQ + r) * DM + h * DK + c4);
            uint2 hh, ll; bsplit4(v, hh, ll);
            *reinterpret_cast<uint2*>(&KH[r * LW + (c4 >> 1)]) = hh;
            *reinterpret_cast<uint2*>(&KL[r * LW + (c4 >> 1)]) = ll;
        }
    }
    __syncthreads();

    const float inv_temp = 0.125f;

    for (int kc = 0; kc < 16; kc++) {
        int buf = kc & 1;
        uint32_t* KH = KVb + buf * 4608;
        uint32_t* KL = KH + 2304;

        float4 stage[4];
        if (kc < 15) {
            #pragma unroll
            for (int it = 0; it < 4; it++) {
                int idx = it * 256 + tid;
                int r = idx >> 4, c4 = (idx & 15) * 4;
                stage[it] = *reinterpret_cast<const float4*>(
                    Kp + (size_t)(b * SEQ + (kc + 1) * 64 + r) * DM + h * DK + c4);
            }
        }

        float c0[4] = {0.f, 0.f, 0.f, 0.f};

        #pragma unroll
        for (int ks = 0; ks < 4; ks++) {
            int kk2 = ks * 8;
            uint32_t aH[4], aL[4], bH[2], bL[2];
            int base = g * LW + kk2 + t;
            aH[0] = QHs[base];     aH[1] = QHs[base + 8 * LW];
            aH[2] = QHs[base + 4]; aH[3] = QHs[base + 8 * LW + 4];
            aL[0] = QLs[base];     aL[1] = QLs[base + 8 * LW];
            aL[2] = QLs[base + 4]; aL[3] = QLs[base + 8 * LW + 4];
            int bb = (n + g) * LW + kk2 + t;
            bH[0] = KH[bb]; bH[1] = KH[bb + 4];
            bL[0] = KL[bb]; bL[1] = KL[bb + 4];
            mma_bf16(c0, aH, bH);
            mma_bf16(c0, aH, bL);
            mma_bf16(c0, aL, bH);
        }

        // epilogue: gate * scale, mask -> S
        {
            int col = kc * 64 + n + 2 * t;
            #pragma unroll
            for (int half = 0; half < 2; half++) {
                int q = g + half * 8;
                const float2 gv = *reinterpret_cast<const float2*>(
                    gate + ((size_t)(b * NHEAD + h) * SEQ + q0 + q) * SEQ + col);
                const int2 mv = *reinterpret_cast<const int2*>(
                    mask + ((size_t)(b * SEQ + q0 + q)) * SEQ + col);
                float s0 = mv.x ? -INFINITY : c0[half * 2 + 0] * inv_temp * gv.x;
                float s1 = mv.y ? -INFINITY : c0[half * 2 + 1] * inv_temp * gv.y;
                *reinterpret_cast<float2*>(&S[q * SLD + col]) = make_float2(s0, s1);
            }
        }

        if (kc < 15) {
            uint32_t* NH = KVb + (buf ^ 1) * 4608;
            uint32_t* NL = NH + 2304;
            #pragma unroll
            for (int it = 0; it < 4; it++) {
                int idx = it * 256 + tid;
                int r = idx >> 4, c4 = (idx & 15) * 4;
                uint2 hh, ll; bsplit4(stage[it], hh, ll);
                *reinterpret_cast<uint2*>(&NH[r * LW + (c4 >> 1)]) = hh;
                *reinterpret_cast<uint2*>(&NL[r * LW + (c4 >> 1)]) = ll;
            }
        }
        __syncthreads();
    }

    // softmax: 8 warps x 2 rows; exp in regs; write attn
    #pragma unroll
    for (int rr = 0; rr < 2; rr++) {
        int r = wid * 2 + rr;
        float* srow = S + r * SLD;
        float4 e[8];
        float mx = -INFINITY;
        #pragma unroll
        for (int i = 0; i < 8; i++) {
            e[i] = *reinterpret_cast<float4*>(&srow[(lane + i * 32) * 4]);
            mx = fmaxf(mx, fmaxf(fmaxf(e[i].x, e[i].y), fmaxf(e[i].z, e[i].w)));
        }
        #pragma unroll
        for (int o = 16; o; o >>= 1) mx = fmaxf(mx, __shfl_xor_sync(0xffffffffu, mx, o));
        float sum = 0.f;
        #pragma unroll
        for (int i = 0; i < 8; i++) {
            e[i].x = __expf(e[i].x - mx); e[i].y = __expf(e[i].y - mx);
            e[i].z = __expf(e[i].z - mx); e[i].w = __expf(e[i].w - mx);
            sum += e[i].x + e[i].y + e[i].z + e[i].w;
        }
        #pragma unroll
        for (int o = 16; o; o >>= 1) sum += __shfl_xor_sync(0xffffffffu, sum, o);
        float inv = 1.f / sum;
        float* arow = attn + ((size_t)(b * NHEAD + h) * SEQ + q0 + r) * SEQ;
        #pragma unroll
        for (int i = 0; i < 8; i++) {
            e[i].x *= inv; e[i].y *= inv; e[i].z *= inv; e[i].w *= inv;
            *reinterpret_cast<float4*>(&arow[(lane + i * 32) * 4]) = e[i];
        }
    }
}

// =====================================================================
// PV GEMM (r6-proven: vt_store transpose, scalar LDS frags)
// =====================================================================
__device__ __forceinline__ void vt_store(uint32_t* VTH, uint32_t* VTL,
                                         float4 v, int kv, int c4, int lane)
{
    float4 p;
    p.x = __shfl_xor_sync(0xffffffffu, v.x, 16);
    p.y = __shfl_xor_sync(0xffffffffu, v.y, 16);
    p.z = __shfl_xor_sync(0xffffffffu, v.z, 16);
    p.w = __shfl_xor_sync(0xffffffffu, v.w, 16);
    int kvp = kv >> 1;
    float e0, o0, e1, o1;
    int d0;
    if ((lane & 16) == 0) { e0 = v.x; o0 = p.x; e1 = v.y; o1 = p.y; d0 = c4; }
    else                  { e0 = p.z; o0 = v.z; e1 = p.w; o1 = v.w; d0 = c4 + 2; }
    uint32_t h, l;
    bsplit2(e0, o0, h, l);
    VTH[d0 * VW + kvp] = h;  VTL[d0 * VW + kvp] = l;
    bsplit2(e1, o1, h, l);
    VTH[(d0 + 1) * VW + kvp] = h;  VTL[(d0 + 1) * VW + kvp] = l;
}

#define PV_SMEM_BYTES ((2 * 128 * LW + 2 * 64 * VW) * 4)   // 54784

__global__ __launch_bounds__(256) void pv_gemm(
    const float* __restrict__ P, const float* __restrict__ Vp,
    float* __restrict__ heads)
{
    extern __shared__ char pvsm[];
    uint32_t* AsH = reinterpret_cast<uint32_t*>(pvsm);
    uint32_t* AsL = AsH + 128 * LW;
    uint32_t* VTH = AsL + 128 * LW;
    uint32_t* VTL = VTH + 64 * VW;

    const int b = blockIdx.z, h = blockIdx.y;
    const int q0 = blockIdx.x * 128;
    const int tid = threadIdx.x;
    const int wid = tid >> 5, lane = tid & 31;
    const int g = lane >> 2, t = lane & 3;
    const int warpM = (wid & 1) * 64;
    const int warpN = (wid >> 1) * 16;

    float c[4][2][4];
    #pragma unroll
    for (int mt = 0; mt < 4; mt++)
        #pragma unroll
        for (int nt = 0; nt < 2; nt++)
            #pragma unroll
            for (int i = 0; i < 4; i++) c[mt][nt][i] = 0.f;

    float4 pa[8], va[4];
    #pragma unroll
    for (int it = 0; it < 8; it++) {
        int idx = it * 256 + tid;
        int r = idx >> 4, c4 = (idx & 15) * 4;
        pa[it] = *reinterpret_cast<const float4*>(
            P + ((size_t)(b * NHEAD + h) * SEQ + q0 + r) * SEQ + c4);
    }
    #pragma unroll
    for (int it = 0; it < 4; it++) {
        int idx = it * 256 + tid;
        int kv = idx >> 4, c4 = (idx & 15) * 4;
        va[it] = *reinterpret_cast<const float4*>(
            Vp + (size_t)(b * SEQ + kv) * DM + h * DK + c4);
    }

    for (int kc = 0; kc < 16; kc++) {
        __syncthreads();
        #pragma unroll
        for (int it = 0; it < 8; it++) {
            int idx = it * 256 + tid;
            int r = idx >> 4, w = (idx & 15) * 2;
            uint2 hh, ll; bsplit4(pa[it], hh, ll);
            *reinterpret_cast<uint2*>(&AsH[r * LW + w]) = hh;
            *reinterpret_cast<uint2*>(&AsL[r * LW + w]) = ll;
        }
        #pragma unroll
        for (int it = 0; it < 4; it++) {
            int idx = it * 256 + tid;
            int kv = idx >> 4, c4 = (idx & 15) * 4;
            vt_store(VTH, VTL, va[it], kv, c4, lane);
        }
        __syncthreads();

        if (kc < 15) {
            #pragma unroll
            for (int it = 0; it < 8; it++) {
                int idx = it * 256 + tid;
                int r = idx >> 4, c4 = (idx & 15) * 4;
                pa[it] = *reinterpret_cast<const float4*>(
                    P + ((size_t)(b * NHEAD + h) * SEQ + q0 + r) * SEQ + (kc + 1) * 64 + c4);
            }
            #pragma unroll
            for (int it = 0; it < 4; it++) {
                int idx = it * 256 + tid;
                int kv = idx >> 4, c4 = (idx & 15) * 4;
                va[it] = *reinterpret_cast<const float4*>(
                    Vp + (size_t)(b * SEQ + (kc + 1) * 64 + kv) * DM + h * DK + c4);
            }
        }

        #pragma unroll
        for (int ks = 0; ks < 4; ks++) {
            int kk2 = ks * 8;
            uint32_t aH[4][4], aL[4][4], bH[2][2], bL[2][2];
            #pragma unroll
            for (int mt = 0; mt < 4; mt++) {
                int base = (warpM + mt * 16 + g) * LW + kk2 + t;
                aH[mt][0] = AsH[base];          aH[mt][1] = AsH[base + 8 * LW];
                aH[mt][2] = AsH[base + 4];      aH[mt][3] = AsH[base + 8 * LW + 4];
                aL[mt][0] = AsL[base];          aL[mt][1] = AsL[base + 8 * LW];
                aL[mt][2] = AsL[base + 4];      aL[mt][3] = AsL[base + 8 * LW + 4];
            }
            #pragma unroll
            for (int nt = 0; nt < 2; nt++) {
                int base = (warpN + nt * 8 + g) * VW + kk2 + t;
                bH[nt][0] = VTH[base]; bH[nt][1] = VTH[base + 4];
                bL[nt][0] = VTL[base]; bL[nt][1] = VTL[base + 4];
            }
            #pragma unroll
            for (int mt = 0; mt < 4; mt++)
                #pragma unroll
                for (int nt = 0; nt < 2; nt++) {
                    mma_bf16(c[mt][nt], aH[mt], bH[nt]);
                    mma_bf16(c[mt][nt], aH[mt], bL[nt]);
                    mma_bf16(c[mt][nt], aL[mt], bH[nt]);
                }
        }
    }

    #pragma unroll
    for (int mt = 0; mt < 4; mt++) {
        int r0 = q0 + warpM + mt * 16 + g;
        int r1 = r0 + 8;
        #pragma unroll
        for (int nt = 0; nt < 2; nt++) {
            int cn = h * DK + warpN + nt * 8 + 2 * t;
            *reinterpret_cast<float2*>(heads + (size_t)(b * SEQ + r0) * DM + cn) =
                make_float2(c[mt][nt][0], c[mt][nt][1]);
            *reinterpret_cast<float2*>(heads + (size_t)(b * SEQ + r1) * DM + cn) =
                make_float2(c[mt][nt][2], c[mt][nt][3]);
        }
    }
}

// ---------------- LayerNorm ----------------
__global__ __launch_bounds__(256) void ln_kernel(
    const float* __restrict__ X, const float* __restrict__ gamma,
    const float* __restrict__ beta, float* __restrict__ out)
{
    __shared__ float sh1[8];
    __shared__ float sh2[8];
    const int row = blockIdx.x;
    const int tid = threadIdx.x;
    const float* x = X + (size_t)row * DM;

    float v[4];
    float s = 0.f;
    #pragma unroll
    for (int i = 0; i < 4; i++) { v[i] = x[tid + i * 256]; s += v[i]; }
    #pragma unroll
    for (int o = 16; o; o >>= 1) s += __shfl_xor_sync(0xffffffffu, s, o);
    if ((tid & 31) == 0) sh1[tid >> 5] = s;
    __syncthreads();
    float tot = 0.f;
    #pragma unroll
    for (int w = 0; w < 8; w++) tot += sh1[w];
    float mu = tot * (1.f / DM);

    float vs = 0.f;
    #pragma unroll
    for (int i = 0; i < 4; i++) { float d = v[i] - mu; vs += d * d; }
    #pragma unroll
    for (int o = 16; o; o >>= 1) vs += __shfl_xor_sync(0xffffffffu, vs, o);
    if ((tid & 31) == 0) sh2[tid >> 5] = vs;
    __syncthreads();
    float tv = 0.f;
    #pragma unroll
    for (int w = 0; w < 8; w++) tv += sh2[w];
    float inv = rsqrtf(tv * (1.f / DM) + LN_EPS);

    float* orow = out + (size_t)row * DM;
    #pragma unroll
    for (int i = 0; i < 4; i++) {
        int c = tid + i * 256;
        orow[c] = (v[i] - mu) * inv * gamma[c] + beta[c];
    }
}

// ---------------- launch ----------------
extern "C" void kernel_launch(void* const* d_in, const int* in_sizes, int n_in,
                              void* d_out, int out_size)
{
    const float* q      = (const float*)d_in[0];
    const float* k      = (const float*)d_in[1];
    const float* v      = (const float*)d_in[2];
    const float* k_gate = (const float*)d_in[3];
    const int*   mask   = (const int*)d_in[4];
    const float* Wq = (const float*)d_in[5];
    const float* bq = (const float*)d_in[6];
    const float* Wk = (const float*)d_in[7];
    const float* bk = (const float*)d_in[8];
    const float* Wv = (const float*)d_in[9];
    const float* bv = (const float*)d_in[10];
    const float* Wo = (const float*)d_in[11];
    const float* bo = (const float*)d_in[12];
    const float* ln_g = (const float*)d_in[13];
    const float* ln_b = (const float*)d_in[14];

    float* out  = (float*)d_out;
    float* attn = out + (size_t)BATCH * SEQ * DM;

    float *Qp, *Kp, *Vp, *heads, *tmp;
    cudaGetSymbolAddress((void**)&Qp, g_Qp);
    cudaGetSymbolAddress((void**)&Kp, g_Kp);
    cudaGetSymbolAddress((void**)&Vp, g_Vp);
    cudaGetSymbolAddress((void**)&heads, g_heads);
    cudaGetSymbolAddress((void**)&tmp, g_tmp);

    cudaFuncSetAttribute(attn_kernel, cudaFuncAttributeMaxDynamicSharedMemorySize,
                         ATTN_SMEM_BYTES);
    cudaFuncSetAttribute(pv_gemm, cudaFuncAttributeMaxDynamicSharedMemorySize,
                         PV_SMEM_BYTES);

    dim3 qkvgrid(DM / 64, MROWS / 128, 3);    // (16, 32, 3)
    qkv_gemm<<<qkvgrid, 256>>>(q, k, v, Wq, Wk, Wv, bq, bk, bv, Qp, Kp, Vp);

    dim3 agrid(SEQ / 16, NHEAD, BATCH);       // (64, 16, 4)
    attn_kernel<<<agrid, 256, ATTN_SMEM_BYTES>>>(Qp, Kp, k_gate, mask, attn);

    dim3 pvgrid(SEQ / 128, NHEAD, BATCH);     // (8, 16, 4)
    pv_gemm<<<pvgrid, 256, PV_SMEM_BYTES>>>(attn, Vp, heads);

    dim3 ogrid(DM / 64, MROWS / 128);         // (16, 32)
    out_gemm<<<ogrid, 256>>>(heads, Wo, bo, q, tmp);

    ln_kernel<<<MROWS, 256>>>(tmp, ln_g, ln_b, out);
}

// round 13
// speedup vs baseline: 1.3324x; 1.3324x over previous
#include <cuda_runtime.h>
#include <cuda_bf16.h>
#include <cstdint>
#include <cmath>

#define BATCH   4
#define SEQ     1024
#define DM      1024
#define NHEAD   16
#define DK      64
#define MROWS   (BATCH*SEQ)
#define LN_EPS  1e-5f

__device__ float g_Qp[MROWS * DM];
__device__ float g_Kp[MROWS * DM];
__device__ float g_Vp[MROWS * DM];
__device__ float g_heads[MROWS * DM];
__device__ float g_tmp[MROWS * DM];

// ---------------- helpers ----------------
__device__ __forceinline__ void bsplit4(float4 v, uint2& h, uint2& l) {
    __nv_bfloat162 h0 = __floats2bfloat162_rn(v.x, v.y);
    __nv_bfloat162 h1 = __floats2bfloat162_rn(v.z, v.w);
    float r0 = v.x - __bfloat162float(h0.x);
    float r1 = v.y - __bfloat162float(h0.y);
    float r2 = v.z - __bfloat162float(h1.x);
    float r3 = v.w - __bfloat162float(h1.y);
    __nv_bfloat162 l0 = __floats2bfloat162_rn(r0, r1);
    __nv_bfloat162 l1 = __floats2bfloat162_rn(r2, r3);
    h.x = *reinterpret_cast<uint32_t*>(&h0);
    h.y = *reinterpret_cast<uint32_t*>(&h1);
    l.x = *reinterpret_cast<uint32_t*>(&l0);
    l.y = *reinterpret_cast<uint32_t*>(&l1);
}

__device__ __forceinline__ void bsplit2(float a, float b, uint32_t& h, uint32_t& l) {
    __nv_bfloat162 hh = __floats2bfloat162_rn(a, b);
    float ra = a - __bfloat162float(hh.x);
    float rb = b - __bfloat162float(hh.y);
    __nv_bfloat162 ll = __floats2bfloat162_rn(ra, rb);
    h = *reinterpret_cast<uint32_t*>(&hh);
    l = *reinterpret_cast<uint32_t*>(&ll);
}

__device__ __forceinline__ void mma_bf16(float* c, const uint32_t* a, const uint32_t* b) {
    asm volatile(
        "mma.sync.aligned.m16n8k16.row.col.f32.bf16.bf16.f32 "
        "{%0,%1,%2,%3}, {%4,%5,%6,%7}, {%8,%9}, {%0,%1,%2,%3};"
        : "+f"(c[0]), "+f"(c[1]), "+f"(c[2]), "+f"(c[3])
        : "r"(a[0]), "r"(a[1]), "r"(a[2]), "r"(a[3]), "r"(b[0]), "r"(b[1]));
}

__device__ __forceinline__ uint32_t smem_u32(const void* p) {
    return (uint32_t)__cvta_generic_to_shared(p);
}
__device__ __forceinline__ void ldsm_x4(uint32_t* r, uint32_t addr) {
    asm volatile("ldmatrix.sync.aligned.m8n8.x4.shared.b16 {%0,%1,%2,%3}, [%4];"
        : "=r"(r[0]), "=r"(r[1]), "=r"(r[2]), "=r"(r[3]) : "r"(addr));
}

// =====================================================================
// bf16x3 GEMM: BM=128, BN=64, BK=32, single-buffered, ldsm fragments.
// This is the R7-measured core (108.6us on out_gemm), verbatim.
// =====================================================================
#define GW 20

#define GEMM_LOAD(k0) do { \
    _Pragma("unroll") \
    for (int it = 0; it < 4; it++) { \
        int idx = it * 256 + tid; int r = idx >> 3, c4 = (idx & 7) * 4; \
        sa[it] = *reinterpret_cast<const float4*>(A + (size_t)(bm + r) * DM + (k0) + c4); \
    } \
    _Pragma("unroll") \
    for (int it = 0; it < 2; it++) { \
        int idx = it * 256 + tid; int r = idx >> 3, c4 = (idx & 7) * 4; \
        sb[it] = *reinterpret_cast<const float4*>(W + (size_t)(bn + r) * DM + (k0) + c4); \
    } \
} while (0)

__device__ __forceinline__ void gemm_core(
    const float* __restrict__ A, const float* __restrict__ W,
    const float* __restrict__ bias, const float* __restrict__ resid,
    float* __restrict__ C, int bm, int bn)
{
    __shared__ uint32_t AsH[128 * GW], AsL[128 * GW];
    __shared__ uint32_t BsH[64 * GW],  BsL[64 * GW];

    const int tid = threadIdx.x;
    const int wid = tid >> 5, lane = tid & 31;
    const int g = lane >> 2, t = lane & 3;
    const int warpM = (wid & 1) * 64;
    const int warpN = (wid >> 1) * 16;

    const uint32_t aoff = (((warpM + (lane & 15)) * GW) + (lane >> 4) * 4) * 4;
    const uint32_t aH_base = smem_u32(AsH) + aoff;
    const uint32_t aL_base = smem_u32(AsL) + aoff;
    const uint32_t boff = (((warpN + (lane & 7) + ((lane >> 4) & 1) * 8) * GW)
                           + ((lane >> 3) & 1) * 4) * 4;
    const uint32_t bH_base = smem_u32(BsH) + boff;
    const uint32_t bL_base = smem_u32(BsL) + boff;

    float c[4][2][4];
    #pragma unroll
    for (int mt = 0; mt < 4; mt++)
        #pragma unroll
        for (int nt = 0; nt < 2; nt++)
            #pragma unroll
            for (int i = 0; i < 4; i++) c[mt][nt][i] = 0.f;

    float4 sa[4], sb[2];
    GEMM_LOAD(0);

    for (int k0 = 0; k0 < DM; k0 += 32) {
        __syncthreads();
        #pragma unroll
        for (int it = 0; it < 4; it++) {
            int idx = it * 256 + tid;
            int r = idx >> 3, w = (idx & 7) * 2;
            uint2 h, l; bsplit4(sa[it], h, l);
            *reinterpret_cast<uint2*>(&AsH[r * GW + w]) = h;
            *reinterpret_cast<uint2*>(&AsL[r * GW + w]) = l;
        }
        #pragma unroll
        for (int it = 0; it < 2; it++) {
            int idx = it * 256 + tid;
            int r = idx >> 3, w = (idx & 7) * 2;
            uint2 h, l; bsplit4(sb[it], h, l);
            *reinterpret_cast<uint2*>(&BsH[r * GW + w]) = h;
            *reinterpret_cast<uint2*>(&BsL[r * GW + w]) = l;
        }
        __syncthreads();

        if (k0 + 32 < DM) GEMM_LOAD(k0 + 32);

        #pragma unroll
        for (int ks = 0; ks < 2; ks++) {
            const uint32_t kb = ks * 32;   // 8 words
            uint32_t aH[4][4], aL[4][4], bH[4], bL[4];
            #pragma unroll
            for (int mt = 0; mt < 4; mt++) {
                ldsm_x4(aH[mt], aH_base + mt * (16 * GW * 4) + kb);
                ldsm_x4(aL[mt], aL_base + mt * (16 * GW * 4) + kb);
            }
            ldsm_x4(bH, bH_base + kb);
            ldsm_x4(bL, bL_base + kb);
            #pragma unroll
            for (int mt = 0; mt < 4; mt++)
                #pragma unroll
                for (int nt = 0; nt < 2; nt++) {
                    mma_bf16(c[mt][nt], aH[mt], bH + nt * 2);
                    mma_bf16(c[mt][nt], aH[mt], bL + nt * 2);
                    mma_bf16(c[mt][nt], aL[mt], bH + nt * 2);
                }
        }
    }

    #pragma unroll
    for (int mt = 0; mt < 4; mt++) {
        int r0 = bm + warpM + mt * 16 + g;
        int r1 = r0 + 8;
        #pragma unroll
        for (int nt = 0; nt < 2; nt++) {
            int cn = bn + warpN + nt * 8 + 2 * t;
            float b0 = bias[cn], b1 = bias[cn + 1];
            float v00 = c[mt][nt][0] + b0, v01 = c[mt][nt][1] + b1;
            float v10 = c[mt][nt][2] + b0, v11 = c[mt][nt][3] + b1;
            if (resid) {
                float2 rA = *reinterpret_cast<const float2*>(resid + (size_t)r0 * DM + cn);
                float2 rB = *reinterpret_cast<const float2*>(resid + (size_t)r1 * DM + cn);
                v00 += rA.x; v01 += rA.y; v10 += rB.x; v11 += rB.y;
            }
            *reinterpret_cast<float2*>(C + (size_t)r0 * DM + cn) = make_float2(v00, v01);
            *reinterpret_cast<float2*>(C + (size_t)r1 * DM + cn) = make_float2(v10, v11);
        }
    }
}

__global__ __launch_bounds__(256) void qkv_gemm(
    const float* __restrict__ q, const float* __restrict__ k, const float* __restrict__ v,
    const float* __restrict__ Wq, const float* __restrict__ Wk, const float* __restrict__ Wv,
    const float* __restrict__ bq, const float* __restrict__ bk, const float* __restrict__ bv,
    float* __restrict__ Qp, float* __restrict__ Kp, float* __restrict__ Vp)
{
    const int z = blockIdx.z;
    const float* A = (z == 0) ? q : (z == 1) ? k : v;
    const float* W = (z == 0) ? Wq : (z == 1) ? Wk : Wv;
    const float* B = (z == 0) ? bq : (z == 1) ? bk : bv;
    float* C = (z == 0) ? Qp : (z == 1) ? Kp : Vp;
    gemm_core(A, W, B, nullptr, C, blockIdx.y * 128, blockIdx.x * 64);
}

__global__ __launch_bounds__(256) void out_gemm(
    const float* __restrict__ A, const float* __restrict__ W,
    const float* __restrict__ bias, const float* __restrict__ resid,
    float* __restrict__ C)
{
    gemm_core(A, W, bias, resid, C, blockIdx.y * 128, blockIdx.x * 64);
}

// =====================================================================
// Attention QK + softmax: block = (b, h, 32 q rows), 256 threads.
// Exact R5-build version (part of the 1046us measurement).
// =====================================================================
#define SLD 1028
#define LW  36
#define VW  35
#define OFF_S   0
#define SZ_S    (32 * SLD * 4)                 // 131584
#define OFF_QP  SZ_S
#define SZ_QP   (2 * 32 * LW * 4)              // 9216
#define OFF_KV  (OFF_QP + SZ_QP)
#define SZ_KV   36864
#define ATTN_SMEM_BYTES (OFF_KV + SZ_KV)       // 177664

__global__ __launch_bounds__(256) void attn_kernel(
    const float* __restrict__ Qp, const float* __restrict__ Kp,
    const float* __restrict__ gate, const int* __restrict__ mask,
    float* __restrict__ attn)
{
    extern __shared__ char smraw[];
    float* S = reinterpret_cast<float*>(smraw + OFF_S);
    uint32_t* QH = reinterpret_cast<uint32_t*>(smraw + OFF_QP);
    uint32_t* QL = QH + 32 * LW;
    uint32_t* KVb = reinterpret_cast<uint32_t*>(smraw + OFF_KV);

    const int b = blockIdx.z, h = blockIdx.y;
    const int q0 = blockIdx.x * 32;
    const int tid = threadIdx.x;
    const int wid = tid >> 5, lane = tid & 31;
    const int g = lane >> 2, t = lane & 3;
    const int n = wid * 8;

    // ---- load Q tile [32][64] -> bf16 hi/lo ----
    #pragma unroll
    for (int it = 0; it < 2; it++) {
        int idx = it * 256 + tid;
        int r = idx >> 4, c4 = (idx & 15) * 4;
        float4 v = *reinterpret_cast<const float4*>(
            Qp + (size_t)(b * SEQ + q0 + r) * DM + h * DK + c4);
        uint2 hh, ll; bsplit4(v, hh, ll);
        *reinterpret_cast<uint2*>(&QH[r * LW + (c4 >> 1)]) = hh;
        *reinterpret_cast<uint2*>(&QL[r * LW + (c4 >> 1)]) = ll;
    }

    // ---- prologue: K chunk 0 -> buf 0 ----
    {
        uint32_t* KH = KVb;            uint32_t* KL = KVb + 2304;
        #pragma unroll
        for (int it = 0; it < 4; it++) {
            int idx = it * 256 + tid;
            int r = idx >> 4, c4 = (idx & 15) * 4;
            float4 v = *reinterpret_cast<const float4*>(
                Kp + (size_t)(b * SEQ + r) * DM + h * DK + c4);
            uint2 hh, ll; bsplit4(v, hh, ll);
            *reinterpret_cast<uint2*>(&KH[r * LW + (c4 >> 1)]) = hh;
            *reinterpret_cast<uint2*>(&KL[r * LW + (c4 >> 1)]) = ll;
        }
    }
    __syncthreads();

    const float inv_temp = 0.125f;

    // ---- QK^T: 16 chunks of 64 kv ----
    for (int kc = 0; kc < 16; kc++) {
        int buf = kc & 1;
        uint32_t* KH = KVb + buf * 4608;
        uint32_t* KL = KH + 2304;

        float4 stage[4];
        if (kc < 15) {
            #pragma unroll
            for (int it = 0; it < 4; it++) {
                int idx = it * 256 + tid;
                int r = idx >> 4, c4 = (idx & 15) * 4;
                stage[it] = *reinterpret_cast<const float4*>(
                    Kp + (size_t)(b * SEQ + (kc + 1) * 64 + r) * DM + h * DK + c4);
            }
        }

        float c0[2][4];
        #pragma unroll
        for (int mt = 0; mt < 2; mt++)
            #pragma unroll
            for (int i = 0; i < 4; i++) c0[mt][i] = 0.f;

        #pragma unroll
        for (int ks = 0; ks < 4; ks++) {
            int kk2 = ks * 8;
            uint32_t aH[2][4], aL[2][4], bH[2], bL[2];
            #pragma unroll
            for (int mt = 0; mt < 2; mt++) {
                int base = (mt * 16 + g) * LW + kk2 + t;
                aH[mt][0] = QH[base];     aH[mt][1] = QH[base + 8 * LW];
                aH[mt][2] = QH[base + 4]; aH[mt][3] = QH[base + 8 * LW + 4];
                aL[mt][0] = QL[base];     aL[mt][1] = QL[base + 8 * LW];
                aL[mt][2] = QL[base + 4]; aL[mt][3] = QL[base + 8 * LW + 4];
            }
            int bb = (n + g) * LW + kk2 + t;
            bH[0] = KH[bb]; bH[1] = KH[bb + 4];
            bL[0] = KL[bb]; bL[1] = KL[bb + 4];
            #pragma unroll
            for (int mt = 0; mt < 2; mt++) {
                mma_bf16(c0[mt], aH[mt], bH);
                mma_bf16(c0[mt], aH[mt], bL);
                mma_bf16(c0[mt], aL[mt], bH);
            }
        }

        // epilogue: gate * scale, mask -> S
        #pragma unroll
        for (int mt = 0; mt < 2; mt++) {
            int col = kc * 64 + n + 2 * t;
            #pragma unroll
            for (int half = 0; half < 2; half++) {
                int q = mt * 16 + g + half * 8;
                const float2 gv = *reinterpret_cast<const float2*>(
                    gate + ((size_t)(b * NHEAD + h) * SEQ + q0 + q) * SEQ + col);
                const int2 mv = *reinterpret_cast<const int2*>(
                    mask + ((size_t)(b * SEQ + q0 + q)) * SEQ + col);
                float s0 = mv.x ? -INFINITY : c0[mt][half * 2 + 0] * inv_temp * gv.x;
                float s1 = mv.y ? -INFINITY : c0[mt][half * 2 + 1] * inv_temp * gv.y;
                *reinterpret_cast<float2*>(&S[q * SLD + col]) = make_float2(s0, s1);
            }
        }

        if (kc < 15) {
            uint32_t* NH = KVb + (buf ^ 1) * 4608;
            uint32_t* NL = NH + 2304;
            #pragma unroll
            for (int it = 0; it < 4; it++) {
                int idx = it * 256 + tid;
                int r = idx >> 4, c4 = (idx & 15) * 4;
                uint2 hh, ll; bsplit4(stage[it], hh, ll);
                *reinterpret_cast<uint2*>(&NH[r * LW + (c4 >> 1)]) = hh;
                *reinterpret_cast<uint2*>(&NL[r * LW + (c4 >> 1)]) = ll;
            }
        }
        __syncthreads();
    }

    // ---- softmax: 8 warps x 4 rows; exp kept in regs; write attn ----
    #pragma unroll
    for (int rr = 0; rr < 4; rr++) {
        int r = wid * 4 + rr;
        float* srow = S + r * SLD;
        float4 e[8];
        float mx = -INFINITY;
        #pragma unroll
        for (int i = 0; i < 8; i++) {
            e[i] = *reinterpret_cast<float4*>(&srow[(lane + i * 32) * 4]);
            mx = fmaxf(mx, fmaxf(fmaxf(e[i].x, e[i].y), fmaxf(e[i].z, e[i].w)));
        }
        #pragma unroll
        for (int o = 16; o; o >>= 1) mx = fmaxf(mx, __shfl_xor_sync(0xffffffffu, mx, o));
        float sum = 0.f;
        #pragma unroll
        for (int i = 0; i < 8; i++) {
            e[i].x = __expf(e[i].x - mx); e[i].y = __expf(e[i].y - mx);
            e[i].z = __expf(e[i].z - mx); e[i].w = __expf(e[i].w - mx);
            sum += e[i].x + e[i].y + e[i].z + e[i].w;
        }
        #pragma unroll
        for (int o = 16; o; o >>= 1) sum += __shfl_xor_sync(0xffffffffu, sum, o);
        float inv = 1.f / sum;
        float* arow = attn + ((size_t)(b * NHEAD + h) * SEQ + q0 + r) * SEQ;
        #pragma unroll
        for (int i = 0; i < 8; i++) {
            e[i].x *= inv; e[i].y *= inv; e[i].z *= inv; e[i].w *= inv;
            *reinterpret_cast<float4*>(&arow[(lane + i * 32) * 4]) = e[i];
        }
    }
}

// =====================================================================
// PV GEMM (R5-build version: vt_store transpose, scalar LDS frags)
// =====================================================================
__device__ __forceinline__ void vt_store(uint32_t* VTH, uint32_t* VTL,
                                         float4 v, int kv, int c4, int lane)
{
    float4 p;
    p.x = __shfl_xor_sync(0xffffffffu, v.x, 16);
    p.y = __shfl_xor_sync(0xffffffffu, v.y, 16);
    p.z = __shfl_xor_sync(0xffffffffu, v.z, 16);
    p.w = __shfl_xor_sync(0xffffffffu, v.w, 16);
    int kvp = kv >> 1;
    float e0, o0, e1, o1;
    int d0;
    if ((lane & 16) == 0) { e0 = v.x; o0 = p.x; e1 = v.y; o1 = p.y; d0 = c4; }
    else                  { e0 = p.z; o0 = v.z; e1 = p.w; o1 = v.w; d0 = c4 + 2; }
    uint32_t h, l;
    bsplit2(e0, o0, h, l);
    VTH[d0 * VW + kvp] = h;  VTL[d0 * VW + kvp] = l;
    bsplit2(e1, o1, h, l);
    VTH[(d0 + 1) * VW + kvp] = h;  VTL[(d0 + 1) * VW + kvp] = l;
}

#define PV_SMEM_BYTES ((2 * 128 * LW + 2 * 64 * VW) * 4)   // 54784

__global__ __launch_bounds__(256) void pv_gemm(
    const float* __restrict__ P, const float* __restrict__ Vp,
    float* __restrict__ heads)
{
    extern __shared__ char pvsm[];
    uint32_t* AsH = reinterpret_cast<uint32_t*>(pvsm);
    uint32_t* AsL = AsH + 128 * LW;
    uint32_t* VTH = AsL + 128 * LW;
    uint32_t* VTL = VTH + 64 * VW;

    const int b = blockIdx.z, h = blockIdx.y;
    const int q0 = blockIdx.x * 128;
    const int tid = threadIdx.x;
    const int wid = tid >> 5, lane = tid & 31;
    const int g = lane >> 2, t = lane & 3;
    const int warpM = (wid & 1) * 64;
    const int warpN = (wid >> 1) * 16;

    float c[4][2][4];
    #pragma unroll
    for (int mt = 0; mt < 4; mt++)
        #pragma unroll
        for (int nt = 0; nt < 2; nt++)
            #pragma unroll
            for (int i = 0; i < 4; i++) c[mt][nt][i] = 0.f;

    float4 pa[8], va[4];
    #pragma unroll
    for (int it = 0; it < 8; it++) {
        int idx = it * 256 + tid;
        int r = idx >> 4, c4 = (idx & 15) * 4;
        pa[it] = *reinterpret_cast<const float4*>(
            P + ((size_t)(b * NHEAD + h) * SEQ + q0 + r) * SEQ + c4);
    }
    #pragma unroll
    for (int it = 0; it < 4; it++) {
        int idx = it * 256 + tid;
        int kv = idx >> 4, c4 = (idx & 15) * 4;
        va[it] = *reinterpret_cast<const float4*>(
            Vp + (size_t)(b * SEQ + kv) * DM + h * DK + c4);
    }

    for (int kc = 0; kc < 16; kc++) {
        __syncthreads();
        #pragma unroll
        for (int it = 0; it < 8; it++) {
            int idx = it * 256 + tid;
            int r = idx >> 4, w = (idx & 15) * 2;
            uint2 hh, ll; bsplit4(pa[it], hh, ll);
            *reinterpret_cast<uint2*>(&AsH[r * LW + w]) = hh;
            *reinterpret_cast<uint2*>(&AsL[r * LW + w]) = ll;
        }
        #pragma unroll
        for (int it = 0; it < 4; it++) {
            int idx = it * 256 + tid;
            int kv = idx >> 4, c4 = (idx & 15) * 4;
            vt_store(VTH, VTL, va[it], kv, c4, lane);
        }
        __syncthreads();

        if (kc < 15) {
            #pragma unroll
            for (int it = 0; it < 8; it++) {
                int idx = it * 256 + tid;
                int r = idx >> 4, c4 = (idx & 15) * 4;
                pa[it] = *reinterpret_cast<const float4*>(
                    P + ((size_t)(b * NHEAD + h) * SEQ + q0 + r) * SEQ + (kc + 1) * 64 + c4);
            }
            #pragma unroll
            for (int it = 0; it < 4; it++) {
                int idx = it * 256 + tid;
                int kv = idx >> 4, c4 = (idx & 15) * 4;
                va[it] = *reinterpret_cast<const float4*>(
                    Vp + (size_t)(b * SEQ + (kc + 1) * 64 + kv) * DM + h * DK + c4);
            }
        }

        #pragma unroll
        for (int ks = 0; ks < 4; ks++) {
            int kk2 = ks * 8;
            uint32_t aH[4][4], aL[4][4], bH[2][2], bL[2][2];
            #pragma unroll
            for (int mt = 0; mt < 4; mt++) {
                int base = (warpM + mt * 16 + g) * LW + kk2 + t;
                aH[mt][0] = AsH[base];          aH[mt][1] = AsH[base + 8 * LW];
                aH[mt][2] = AsH[base + 4];      aH[mt][3] = AsH[base + 8 * LW + 4];
                aL[mt][0] = AsL[base];          aL[mt][1] = AsL[base + 8 * LW];
                aL[mt][2] = AsL[base + 4];      aL[mt][3] = AsL[base + 8 * LW + 4];
            }
            #pragma unroll
            for (int nt = 0; nt < 2; nt++) {
                int base = (warpN + nt * 8 + g) * VW + kk2 + t;
                bH[nt][0] = VTH[base]; bH[nt][1] = VTH[base + 4];
                bL[nt][0] = VTL[base]; bL[nt][1] = VTL[base + 4];
            }
            #pragma unroll
            for (int mt = 0; mt < 4; mt++)
                #pragma unroll
                for (int nt = 0; nt < 2; nt++) {
                    mma_bf16(c[mt][nt], aH[mt], bH[nt]);
                    mma_bf16(c[mt][nt], aH[mt], bL[nt]);
                    mma_bf16(c[mt][nt], aL[mt], bH[nt]);
                }
        }
    }

    #pragma unroll
    for (int mt = 0; mt < 4; mt++) {
        int r0 = q0 + warpM + mt * 16 + g;
        int r1 = r0 + 8;
        #pragma unroll
        for (int nt = 0; nt < 2; nt++) {
            int cn = h * DK + warpN + nt * 8 + 2 * t;
            *reinterpret_cast<float2*>(heads + (size_t)(b * SEQ + r0) * DM + cn) =
                make_float2(c[mt][nt][0], c[mt][nt][1]);
            *reinterpret_cast<float2*>(heads + (size_t)(b * SEQ + r1) * DM + cn) =
                make_float2(c[mt][nt][2], c[mt][nt][3]);
        }
    }
}

// ---------------- LayerNorm ----------------
__global__ __launch_bounds__(256) void ln_kernel(
    const float* __restrict__ X, const float* __restrict__ gamma,
    const float* __restrict__ beta, float* __restrict__ out)
{
    __shared__ float sh1[8];
    __shared__ float sh2[8];
    const int row = blockIdx.x;
    const int tid = threadIdx.x;
    const float* x = X + (size_t)row * DM;

    float v[4];
    float s = 0.f;
    #pragma unroll
    for (int i = 0; i < 4; i++) { v[i] = x[tid + i * 256]; s += v[i]; }
    #pragma unroll
    for (int o = 16; o; o >>= 1) s += __shfl_xor_sync(0xffffffffu, s, o);
    if ((tid & 31) == 0) sh1[tid >> 5] = s;
    __syncthreads();
    float tot = 0.f;
    #pragma unroll
    for (int w = 0; w < 8; w++) tot += sh1[w];
    float mu = tot * (1.f / DM);

    float vs = 0.f;
    #pragma unroll
    for (int i = 0; i < 4; i++) { float d = v[i] - mu; vs += d * d; }
    #pragma unroll
    for (int o = 16; o; o >>= 1) vs += __shfl_xor_sync(0xffffffffu, vs, o);
    if ((tid & 31) == 0) sh2[tid >> 5] = vs;
    __syncthreads();
    float tv = 0.f;
    #pragma unroll
    for (int w = 0; w < 8; w++) tv += sh2[w];
    float inv = rsqrtf(tv * (1.f / DM) + LN_EPS);

    float* orow = out + (size_t)row * DM;
    #pragma unroll
    for (int i = 0; i < 4; i++) {
        int c = tid + i * 256;
        orow[c] = (v[i] - mu) * inv * gamma[c] + beta[c];
    }
}

// ---------------- launch ----------------
extern "C" void kernel_launch(void* const* d_in, const int* in_sizes, int n_in,
                              void* d_out, int out_size)
{
    const float* q      = (const float*)d_in[0];
    const float* k      = (const float*)d_in[1];
    const float* v      = (const float*)d_in[2];
    const float* k_gate = (const float*)d_in[3];
    const int*   mask   = (const int*)d_in[4];
    const float* Wq = (const float*)d_in[5];
    const float* bq = (const float*)d_in[6];
    const float* Wk = (const float*)d_in[7];
    const float* bk = (const float*)d_in[8];
    const float* Wv = (const float*)d_in[9];
    const float* bv = (const float*)d_in[10];
    const float* Wo = (const float*)d_in[11];
    const float* bo = (const float*)d_in[12];
    const float* ln_g = (const float*)d_in[13];
    const float* ln_b = (const float*)d_in[14];

    float* out  = (float*)d_out;
    float* attn = out + (size_t)BATCH * SEQ * DM;

    float *Qp, *Kp, *Vp, *heads, *tmp;
    cudaGetSymbolAddress((void**)&Qp, g_Qp);
    cudaGetSymbolAddress((void**)&Kp, g_Kp);
    cudaGetSymbolAddress((void**)&Vp, g_Vp);
    cudaGetSymbolAddress((void**)&heads, g_heads);
    cudaGetSymbolAddress((void**)&tmp, g_tmp);

    cudaFuncSetAttribute(attn_kernel, cudaFuncAttributeMaxDynamicSharedMemorySize,
                         ATTN_SMEM_BYTES);
    cudaFuncSetAttribute(pv_gemm, cudaFuncAttributeMaxDynamicSharedMemorySize,
                         PV_SMEM_BYTES);

    dim3 qkvgrid(DM / 64, MROWS / 128, 3);    // (16, 32, 3)
    qkv_gemm<<<qkvgrid, 256>>>(q, k, v, Wq, Wk, Wv, bq, bk, bv, Qp, Kp, Vp);

    dim3 agrid(SEQ / 32, NHEAD, BATCH);       // (32, 16, 4)
    attn_kernel<<<agrid, 256, ATTN_SMEM_BYTES>>>(Qp, Kp, k_gate, mask, attn);

    dim3 pvgrid(SEQ / 128, NHEAD, BATCH);     // (8, 16, 4)
    pv_gemm<<<pvgrid, 256, PV_SMEM_BYTES>>>(attn, Vp, heads);

    dim3 ogrid(DM / 64, MROWS / 128);         // (16, 32)
    out_gemm<<<ogrid, 256>>>(heads, Wo, bo, q, tmp);

    ln_kernel<<<MROWS, 256>>>(tmp, ln_g, ln_b, out);
}